// round 7
// baseline (speedup 1.0000x reference)
#include <cuda_runtime.h>
#include <cuda_bf16.h>
#include <cstdint>
#include <cstddef>

#define NN 100000
#define NE 1600000
#define HD 128
#define VC 1000
#define VP 1024
#define NL 3

// ---------------------------------------------------------------------------
// Device scratch (static __device__ arrays; no allocations allowed)
// ---------------------------------------------------------------------------
__device__ __align__(256) float         g_h[(size_t)NN * HD];        // fp32 node features
__device__ __align__(256) __nv_bfloat16 g_Ahi[(size_t)NN * 2 * HD];  // [N,256]: cols 0..127 = mean, 128..255 = self (hi)
__device__ __align__(256) __nv_bfloat16 g_Alo[(size_t)NN * 2 * HD];  // lo parts
__device__ __align__(256) __nv_bfloat16 g_Bhi[NL * HD * 2 * HD];     // [l][n][k] combined [Wl;Wr]^T, K-major, hi
__device__ __align__(256) __nv_bfloat16 g_Blo[NL * HD * 2 * HD];
__device__ __align__(256) __nv_bfloat16 g_BLhi[VP * HD];             // [n][k] Wlast^T (n padded to 1024), hi
__device__ __align__(256) __nv_bfloat16 g_BLlo[VP * HD];
__device__ int g_deg[NN];
__device__ int g_cursor[NN];
__device__ int g_rowptr[NN + 1];
__device__ int g_csrsrc[NE];
__device__ int g_bsum[256];
__device__ int g_boff[256];

// ---------------------------------------------------------------------------
// HMMA helpers (sm_80 baseline features only -- target is sm_103 non-'a')
// ---------------------------------------------------------------------------
__device__ __forceinline__ uint32_t smem_to_u32(const void* p) {
    uint32_t a;
    asm("{ .reg .u64 t; cvta.to.shared.u64 t, %1; cvt.u32.u64 %0, t; }" : "=r"(a) : "l"(p));
    return a;
}
__device__ __forceinline__ uint32_t swz(uint32_t o) { return o ^ ((o >> 3) & 0x70); }

__device__ __forceinline__ void ldsm4(uint32_t* r, uint32_t addr) {
    asm volatile("ldmatrix.sync.aligned.m8n8.x4.shared.b16 {%0,%1,%2,%3}, [%4];"
                 : "=r"(r[0]), "=r"(r[1]), "=r"(r[2]), "=r"(r[3]) : "r"(addr));
}
__device__ __forceinline__ void mma_bf16(float* d, const uint32_t* a, const uint32_t* b) {
    asm volatile(
        "mma.sync.aligned.m16n8k16.row.col.f32.bf16.bf16.f32 "
        "{%0,%1,%2,%3}, {%4,%5,%6,%7}, {%8,%9}, {%0,%1,%2,%3};"
        : "+f"(d[0]), "+f"(d[1]), "+f"(d[2]), "+f"(d[3])
        : "r"(a[0]), "r"(a[1]), "r"(a[2]), "r"(a[3]), "r"(b[0]), "r"(b[1]));
}

// ---------------------------------------------------------------------------
// Small kernels: init / embed / weight prep / CSR build
// ---------------------------------------------------------------------------
__global__ void k_zero() {
    int i = blockIdx.x * blockDim.x + threadIdx.x;
    if (i < NN) { g_deg[i] = 0; g_cursor[i] = 0; }
}

__global__ void k_embed(const int* __restrict__ x, const float* __restrict__ emb) {
    int idx = blockIdx.x * blockDim.x + threadIdx.x;  // NN*32 threads, float4 each
    if (idx >= NN * 32) return;
    int n = idx >> 5, q = idx & 31;
    float4 v = reinterpret_cast<const float4*>(emb + (size_t)x[n] * HD)[q];
    reinterpret_cast<float4*>(g_h + (size_t)n * HD)[q] = v;
    size_t o = (size_t)n * 256 + 128 + q * 4;
    float vv[4] = {v.x, v.y, v.z, v.w};
#pragma unroll
    for (int j = 0; j < 4; j++) {
        __nv_bfloat16 hi = __float2bfloat16(vv[j]);
        g_Ahi[o + j] = hi;
        g_Alo[o + j] = __float2bfloat16(vv[j] - __bfloat162float(hi));
    }
}

__global__ void k_prep_w(const float* __restrict__ Wl, const float* __restrict__ Wr,
                         const float* __restrict__ Wlast) {
    int idx = blockIdx.x * blockDim.x + threadIdx.x;
    if (idx < NL * HD * 2 * HD) {  // [l][n][k], k in 0..255
        int l = idx / (HD * 2 * HD);
        int rem = idx % (HD * 2 * HD);
        int n = rem / 256, k = rem % 256;
        float w = (k < HD) ? Wl[l * HD * HD + k * HD + n] : Wr[l * HD * HD + (k - HD) * HD + n];
        __nv_bfloat16 hi = __float2bfloat16(w);
        g_Bhi[idx] = hi;
        g_Blo[idx] = __float2bfloat16(w - __bfloat162float(hi));
    } else {
        int i2 = idx - NL * HD * 2 * HD;
        if (i2 >= VP * HD) return;
        int n = i2 / HD, k = i2 % HD;
        float w = (n < VC) ? Wlast[(size_t)k * VC + n] : 0.0f;
        __nv_bfloat16 hi = __float2bfloat16(w);
        g_BLhi[i2] = hi;
        g_BLlo[i2] = __float2bfloat16(w - __bfloat162float(hi));
    }
}

__global__ void k_deg(const int* __restrict__ dst) {
    int e = blockIdx.x * blockDim.x + threadIdx.x;
    if (e < NE) atomicAdd(&g_deg[dst[e]], 1);
}

#define SCAN_CH 512
#define SCAN_NB 196  // ceil(100000/512)

__global__ void k_scan_partial() {
    __shared__ int sh[SCAN_CH];
    int b = blockIdx.x, t = threadIdx.x;
    int i = b * SCAN_CH + t;
    sh[t] = (i < NN) ? g_deg[i] : 0;
    for (int s = SCAN_CH / 2; s > 0; s >>= 1) {
        __syncthreads();
        if (t < s) sh[t] += sh[t + s];
    }
    if (t == 0) g_bsum[b] = sh[0];
}

__global__ void k_scan_top() {
    __shared__ int sh[256];
    int t = threadIdx.x;
    int v = (t < SCAN_NB) ? g_bsum[t] : 0;
    sh[t] = v;
    __syncthreads();
    for (int off = 1; off < 256; off <<= 1) {
        int a = (t >= off) ? sh[t - off] : 0;
        __syncthreads();
        sh[t] += a;
        __syncthreads();
    }
    g_boff[t] = sh[t] - v;  // exclusive
    if (t == 0) g_rowptr[NN] = NE;
}

__global__ void k_scan_apply() {
    __shared__ int sh[SCAN_CH];
    int b = blockIdx.x, t = threadIdx.x;
    int i = b * SCAN_CH + t;
    int v = (i < NN) ? g_deg[i] : 0;
    sh[t] = v;
    __syncthreads();
    for (int off = 1; off < SCAN_CH; off <<= 1) {
        int a = (t >= off) ? sh[t - off] : 0;
        __syncthreads();
        sh[t] += a;
        __syncthreads();
    }
    if (i < NN) g_rowptr[i] = g_boff[b] + sh[t] - v;  // exclusive global prefix
}

__global__ void k_fill(const int* __restrict__ src, const int* __restrict__ dst) {
    int e = blockIdx.x * blockDim.x + threadIdx.x;
    if (e >= NE) return;
    int d = dst[e];
    int pos = g_rowptr[d] + atomicAdd(&g_cursor[d], 1);
    g_csrsrc[pos] = src[e];
}

// ---------------------------------------------------------------------------
// Aggregation: warp per node, float4 per lane, gather-only
// ---------------------------------------------------------------------------
__global__ void __launch_bounds__(256) k_agg() {
    int w = blockIdx.x * 8 + (threadIdx.x >> 5);
    if (w >= NN) return;
    int lane = threadIdx.x & 31;
    int beg = g_rowptr[w], end = g_rowptr[w + 1];
    float4 acc = make_float4(0.f, 0.f, 0.f, 0.f);
    for (int e = beg; e < end; e++) {
        int s = g_csrsrc[e];
        float4 v = reinterpret_cast<const float4*>(g_h + (size_t)s * HD)[lane];
        acc.x += v.x; acc.y += v.y; acc.z += v.z; acc.w += v.w;
    }
    int cnt = end - beg;
    float inv = 1.0f / (float)(cnt > 0 ? cnt : 1);
    float vv[4] = {acc.x * inv, acc.y * inv, acc.z * inv, acc.w * inv};
    size_t o = (size_t)w * 256 + lane * 4;
#pragma unroll
    for (int j = 0; j < 4; j++) {
        __nv_bfloat16 hi = __float2bfloat16(vv[j]);
        g_Ahi[o + j] = hi;
        g_Alo[o + j] = __float2bfloat16(vv[j] - __bfloat162float(hi));
    }
}

// ---------------------------------------------------------------------------
// GEMM core: 256 threads, CTA tile 128(M) x 128(N), K chunks of 64 staged in
// swizzled smem. Warp tile 64x32 (2x4 warp grid). bf16 hi/lo 3-term split.
// SMEM layout: AHI 0, ALO 16K, BHI 32K, BLO 48K  (total 64KB dynamic)
// ---------------------------------------------------------------------------
#define SM_AHI 0
#define SM_ALO 16384
#define SM_BHI 32768
#define SM_BLO 49152
#define SM_BYTES 65536

struct Frags {
    float acc[4][4][4];
};

__device__ __forceinline__ void gemm_chunk_compute(uint32_t sb, int wid, int lane,
                                                   float acc[4][4][4]) {
    int m_base = (wid >> 2) * 64;
    int n_base = (wid & 3) * 32;
#pragma unroll
    for (int ks = 0; ks < 4; ks++) {
        uint32_t a_hi[4][4], a_lo[4][4];
#pragma unroll
        for (int mt = 0; mt < 4; mt++) {
            int row = m_base + mt * 16 + (lane & 15);
            int col = ks * 16 + ((lane >> 4) << 3);
            uint32_t ad = sb + SM_AHI + swz((uint32_t)(row * 128 + col * 2));
            ldsm4(a_hi[mt], ad);
            ldsm4(a_lo[mt], ad + (SM_ALO - SM_AHI));
        }
        uint32_t b_hi[2][4], b_lo[2][4];
#pragma unroll
        for (int nt2 = 0; nt2 < 2; nt2++) {
            int nrow = n_base + nt2 * 16 + (lane & 7) + (((lane >> 4) & 1) << 3);
            int col = ks * 16 + (((lane >> 3) & 1) << 3);
            uint32_t bd = sb + SM_BHI + swz((uint32_t)(nrow * 128 + col * 2));
            ldsm4(b_hi[nt2], bd);
            ldsm4(b_lo[nt2], bd + (SM_BLO - SM_BHI));
        }
#pragma unroll
        for (int mt = 0; mt < 4; mt++) {
#pragma unroll
            for (int nt = 0; nt < 4; nt++) {
                const uint32_t* bh = &b_hi[nt >> 1][(nt & 1) * 2];
                const uint32_t* bl = &b_lo[nt >> 1][(nt & 1) * 2];
                mma_bf16(acc[mt][nt], a_hi[mt], bh);
                mma_bf16(acc[mt][nt], a_lo[mt], bh);
                mma_bf16(acc[mt][nt], a_hi[mt], bl);
            }
        }
    }
}

// Layer GEMM: A = g_A(hi/lo) full 256 cols (mean||self), B = g_B(hi/lo)[layer],
// epilogue: bias + relu -> g_h, g_Ahi/g_Alo self halves.
__global__ void __launch_bounds__(256) k_layer_gemm(const float* __restrict__ bias, int layer) {
    extern __shared__ __align__(1024) char smem[];
    uint32_t sb = smem_to_u32(smem);
    int tid = threadIdx.x, wid = tid >> 5, lane = tid & 31;
    int base = blockIdx.x * 128;

    const __nv_bfloat16* Bh = g_Bhi + (size_t)layer * HD * 256;
    const __nv_bfloat16* Bl = g_Blo + (size_t)layer * HD * 256;

    float acc[4][4][4];
#pragma unroll
    for (int i = 0; i < 4; i++)
#pragma unroll
        for (int j = 0; j < 4; j++)
#pragma unroll
            for (int q = 0; q < 4; q++) acc[i][j][q] = 0.f;

    for (int kc = 0; kc < 4; kc++) {
        int k0 = kc * 64;
        if (kc) __syncthreads();  // protect previous chunk's reads
        for (int idx = tid; idx < 1024; idx += 256) {
            int r = idx >> 3, s = idx & 7;
            int node = base + r; if (node >= NN) node = NN - 1;
            size_t ga = (size_t)node * 256 + k0 + s * 8;
            size_t gb = (size_t)r * 256 + k0 + s * 8;
            uint32_t so = swz((uint32_t)(r * 128 + s * 16));
            *reinterpret_cast<uint4*>(smem + SM_AHI + so) = *reinterpret_cast<const uint4*>(g_Ahi + ga);
            *reinterpret_cast<uint4*>(smem + SM_ALO + so) = *reinterpret_cast<const uint4*>(g_Alo + ga);
            *reinterpret_cast<uint4*>(smem + SM_BHI + so) = *reinterpret_cast<const uint4*>(Bh + gb);
            *reinterpret_cast<uint4*>(smem + SM_BLO + so) = *reinterpret_cast<const uint4*>(Bl + gb);
        }
        __syncthreads();
        gemm_chunk_compute(sb, wid, lane, acc);
    }

    // Epilogue: bias + relu, write fp32 + hi/lo bf16 self features
    int gid = lane >> 2, itg = lane & 3;
    int m_base = (wid >> 2) * 64, n_base = (wid & 3) * 32;
#pragma unroll
    for (int mt = 0; mt < 4; mt++) {
#pragma unroll
        for (int nt = 0; nt < 4; nt++) {
            int col = n_base + nt * 8 + itg * 2;
            float b0 = bias[col], b1 = bias[col + 1];
#pragma unroll
            for (int half = 0; half < 2; half++) {
                int node = base + m_base + mt * 16 + gid + half * 8;
                if (node >= NN) continue;
                float v0 = acc[mt][nt][half * 2 + 0] + b0;
                float v1 = acc[mt][nt][half * 2 + 1] + b1;
                v0 = v0 > 0.f ? v0 : 0.f;
                v1 = v1 > 0.f ? v1 : 0.f;
                *reinterpret_cast<float2*>(g_h + (size_t)node * HD + col) = make_float2(v0, v1);
                __nv_bfloat16 h0 = __float2bfloat16(v0), h1 = __float2bfloat16(v1);
                __nv_bfloat16 l0 = __float2bfloat16(v0 - __bfloat162float(h0));
                __nv_bfloat16 l1 = __float2bfloat16(v1 - __bfloat162float(h1));
                size_t o = (size_t)node * 256 + 128 + col;
                *reinterpret_cast<__nv_bfloat162*>(&g_Ahi[o]) = __nv_bfloat162{h0, h1};
                *reinterpret_cast<__nv_bfloat162*>(&g_Alo[o]) = __nv_bfloat162{l0, l1};
            }
        }
    }
}

// Final GEMM: logits tile 128(M) x 128(N of vocab), K = 128 (self features),
// epilogue: + blast, write to d_out (cols < 1000).
__global__ void __launch_bounds__(256) k_final_gemm(const float* __restrict__ blast,
                                                    float* __restrict__ out) {
    extern __shared__ __align__(1024) char smem[];
    uint32_t sb = smem_to_u32(smem);
    int tid = threadIdx.x, wid = tid >> 5, lane = tid & 31;
    int base = blockIdx.x * 128;
    int ncol0 = blockIdx.y * 128;

    float acc[4][4][4];
#pragma unroll
    for (int i = 0; i < 4; i++)
#pragma unroll
        for (int j = 0; j < 4; j++)
#pragma unroll
            for (int q = 0; q < 4; q++) acc[i][j][q] = 0.f;

    for (int kc = 0; kc < 2; kc++) {
        int k0 = kc * 64;
        if (kc) __syncthreads();
        for (int idx = tid; idx < 1024; idx += 256) {
            int r = idx >> 3, s = idx & 7;
            int node = base + r; if (node >= NN) node = NN - 1;
            size_t ga = (size_t)node * 256 + 128 + k0 + s * 8;
            size_t gb = (size_t)(ncol0 + r) * HD + k0 + s * 8;
            uint32_t so = swz((uint32_t)(r * 128 + s * 16));
            *reinterpret_cast<uint4*>(smem + SM_AHI + so) = *reinterpret_cast<const uint4*>(g_Ahi + ga);
            *reinterpret_cast<uint4*>(smem + SM_ALO + so) = *reinterpret_cast<const uint4*>(g_Alo + ga);
            *reinterpret_cast<uint4*>(smem + SM_BHI + so) = *reinterpret_cast<const uint4*>(g_BLhi + gb);
            *reinterpret_cast<uint4*>(smem + SM_BLO + so) = *reinterpret_cast<const uint4*>(g_BLlo + gb);
        }
        __syncthreads();
        gemm_chunk_compute(sb, wid, lane, acc);
    }

    int gid = lane >> 2, itg = lane & 3;
    int m_base = (wid >> 2) * 64, n_base = (wid & 3) * 32;
#pragma unroll
    for (int mt = 0; mt < 4; mt++) {
#pragma unroll
        for (int nt = 0; nt < 4; nt++) {
            int col = ncol0 + n_base + nt * 8 + itg * 2;
            if (col >= VC) continue;
            float b0 = blast[col];
            float b1 = (col + 1 < VC) ? blast[col + 1] : 0.f;
#pragma unroll
            for (int half = 0; half < 2; half++) {
                int node = base + m_base + mt * 16 + gid + half * 8;
                if (node >= NN) continue;
                float v0 = acc[mt][nt][half * 2 + 0] + b0;
                float v1 = acc[mt][nt][half * 2 + 1] + b1;
                size_t o = (size_t)node * VC + col;
                out[o] = v0;
                if (col + 1 < VC) out[o + 1] = v1;
            }
        }
    }
}

// ---------------------------------------------------------------------------
// Softmax: warp per row, 1000 cols held in registers (32 per lane)
// ---------------------------------------------------------------------------
__global__ void __launch_bounds__(256) k_softmax(float* __restrict__ out) {
    int w = blockIdx.x * 8 + (threadIdx.x >> 5);
    if (w >= NN) return;
    int lane = threadIdx.x & 31;
    float r[32];
    float mx = -1e30f;
    float* row = out + (size_t)w * VC;
#pragma unroll
    for (int i = 0; i < 32; i++) {
        int c = lane + i * 32;
        float v = (c < VC) ? row[c] : -1e30f;
        r[i] = v;
        mx = fmaxf(mx, v);
    }
#pragma unroll
    for (int o = 16; o > 0; o >>= 1) mx = fmaxf(mx, __shfl_xor_sync(0xFFFFFFFF, mx, o));
    float sum = 0.f;
#pragma unroll
    for (int i = 0; i < 32; i++) {
        int c = lane + i * 32;
        if (c < VC) { r[i] = __expf(r[i] - mx); sum += r[i]; }
    }
#pragma unroll
    for (int o = 16; o > 0; o >>= 1) sum += __shfl_xor_sync(0xFFFFFFFF, sum, o);
    float inv = 1.0f / sum;
#pragma unroll
    for (int i = 0; i < 32; i++) {
        int c = lane + i * 32;
        if (c < VC) row[c] = r[i] * inv;
    }
}

// ---------------------------------------------------------------------------
// Launch
// ---------------------------------------------------------------------------
extern "C" void kernel_launch(void* const* d_in, const int* in_sizes, int n_in,
                              void* d_out, int out_size) {
    const int*   x     = (const int*)d_in[0];
    const int*   ei    = (const int*)d_in[1];
    const float* emb   = (const float*)d_in[2];
    const float* Wl    = (const float*)d_in[3];
    const float* bl    = (const float*)d_in[4];
    const float* Wr    = (const float*)d_in[5];
    const float* Wlast = (const float*)d_in[6];
    const float* blast = (const float*)d_in[7];
    float* out = (float*)d_out;
    const int* src = ei;
    const int* dst = ei + NE;

    cudaFuncSetAttribute(k_layer_gemm, cudaFuncAttributeMaxDynamicSharedMemorySize, SM_BYTES);
    cudaFuncSetAttribute(k_final_gemm, cudaFuncAttributeMaxDynamicSharedMemorySize, SM_BYTES);

    k_zero<<<(NN + 255) / 256, 256>>>();
    k_embed<<<(NN * 32 + 255) / 256, 256>>>(x, emb);
    k_prep_w<<<(NL * HD * 2 * HD + VP * HD + 255) / 256, 256>>>(Wl, Wr, Wlast);
    k_deg<<<(NE + 255) / 256, 256>>>(dst);
    k_scan_partial<<<SCAN_NB, SCAN_CH>>>();
    k_scan_top<<<1, 256>>>();
    k_scan_apply<<<SCAN_NB, SCAN_CH>>>();
    k_fill<<<(NE + 255) / 256, 256>>>(src, dst);

    int nb = (NN + 127) / 128;
    for (int l = 0; l < NL; l++) {
        k_agg<<<(NN + 7) / 8, 256>>>();
        k_layer_gemm<<<nb, 256, SM_BYTES>>>(bl + l * HD, l);
    }

    dim3 fgrid(nb, VP / 128);
    k_final_gemm<<<fgrid, 256, SM_BYTES>>>(blast, out);
    k_softmax<<<(NN + 7) / 8, 256>>>(out);
}

// round 8
// speedup vs baseline: 1.3217x; 1.3217x over previous
#include <cuda_runtime.h>
#include <cuda_bf16.h>
#include <cstdint>
#include <cstddef>

#define NN 100000
#define NE 1600000
#define HD 128
#define VC 1000
#define VP 1024
#define NL 3

// ---------------------------------------------------------------------------
// Device scratch (static __device__ arrays; no allocations allowed)
// ---------------------------------------------------------------------------
__device__ __align__(256) float         g_h[(size_t)NN * HD];        // fp32 node features
__device__ __align__(256) __nv_bfloat16 g_Ahi[(size_t)NN * 2 * HD];  // [N,256]: cols 0..127 = mean, 128..255 = self (hi)
__device__ __align__(256) __nv_bfloat16 g_Alo[(size_t)NN * 2 * HD];  // lo parts
__device__ __align__(256) __nv_bfloat16 g_Bhi[NL * HD * 2 * HD];     // [l][n][k] combined [Wl;Wr]^T, K-major, hi
__device__ __align__(256) __nv_bfloat16 g_Blo[NL * HD * 2 * HD];
__device__ __align__(256) __nv_bfloat16 g_BLhi[VP * HD];             // [n][k] Wlast^T (n padded to 1024), hi
__device__ __align__(256) __nv_bfloat16 g_BLlo[VP * HD];
__device__ int g_deg[NN];
__device__ int g_cursor[NN];
__device__ int g_rowptr[NN + 1];
__device__ int g_csrsrc[NE];
__device__ int g_bsum[256];
__device__ int g_boff[256];

// ---------------------------------------------------------------------------
// HMMA helpers (sm_80 baseline features only -- target is sm_103 non-'a')
// ---------------------------------------------------------------------------
__device__ __forceinline__ uint32_t smem_to_u32(const void* p) {
    uint32_t a;
    asm("{ .reg .u64 t; cvta.to.shared.u64 t, %1; cvt.u32.u64 %0, t; }" : "=r"(a) : "l"(p));
    return a;
}
__device__ __forceinline__ uint32_t swz(uint32_t o) { return o ^ ((o >> 3) & 0x70); }

__device__ __forceinline__ void ldsm4(uint32_t* r, uint32_t addr) {
    asm volatile("ldmatrix.sync.aligned.m8n8.x4.shared.b16 {%0,%1,%2,%3}, [%4];"
                 : "=r"(r[0]), "=r"(r[1]), "=r"(r[2]), "=r"(r[3]) : "r"(addr));
}
__device__ __forceinline__ void mma_bf16(float* d, const uint32_t* a, const uint32_t* b) {
    asm volatile(
        "mma.sync.aligned.m16n8k16.row.col.f32.bf16.bf16.f32 "
        "{%0,%1,%2,%3}, {%4,%5,%6,%7}, {%8,%9}, {%0,%1,%2,%3};"
        : "+f"(d[0]), "+f"(d[1]), "+f"(d[2]), "+f"(d[3])
        : "r"(a[0]), "r"(a[1]), "r"(a[2]), "r"(a[3]), "r"(b[0]), "r"(b[1]));
}

// ---------------------------------------------------------------------------
// Small kernels: init / embed / weight prep / CSR build
// ---------------------------------------------------------------------------
__global__ void k_zero() {
    int i = blockIdx.x * blockDim.x + threadIdx.x;
    if (i < NN) { g_deg[i] = 0; g_cursor[i] = 0; }
}

__global__ void k_embed(const int* __restrict__ x, const float* __restrict__ emb) {
    int idx = blockIdx.x * blockDim.x + threadIdx.x;  // NN*32 threads, float4 each
    if (idx >= NN * 32) return;
    int n = idx >> 5, q = idx & 31;
    float4 v = reinterpret_cast<const float4*>(emb + (size_t)x[n] * HD)[q];
    reinterpret_cast<float4*>(g_h + (size_t)n * HD)[q] = v;
    size_t o = (size_t)n * 256 + 128 + q * 4;
    float vv[4] = {v.x, v.y, v.z, v.w};
#pragma unroll
    for (int j = 0; j < 4; j++) {
        __nv_bfloat16 hi = __float2bfloat16(vv[j]);
        g_Ahi[o + j] = hi;
        g_Alo[o + j] = __float2bfloat16(vv[j] - __bfloat162float(hi));
    }
}

__global__ void k_prep_w(const float* __restrict__ Wl, const float* __restrict__ Wr,
                         const float* __restrict__ Wlast) {
    int idx = blockIdx.x * blockDim.x + threadIdx.x;
    if (idx < NL * HD * 2 * HD) {  // [l][n][k], k in 0..255
        int l = idx / (HD * 2 * HD);
        int rem = idx % (HD * 2 * HD);
        int n = rem / 256, k = rem % 256;
        float w = (k < HD) ? Wl[l * HD * HD + k * HD + n] : Wr[l * HD * HD + (k - HD) * HD + n];
        __nv_bfloat16 hi = __float2bfloat16(w);
        g_Bhi[idx] = hi;
        g_Blo[idx] = __float2bfloat16(w - __bfloat162float(hi));
    } else {
        int i2 = idx - NL * HD * 2 * HD;
        if (i2 >= VP * HD) return;
        int n = i2 / HD, k = i2 % HD;
        float w = (n < VC) ? Wlast[(size_t)k * VC + n] : 0.0f;
        __nv_bfloat16 hi = __float2bfloat16(w);
        g_BLhi[i2] = hi;
        g_BLlo[i2] = __float2bfloat16(w - __bfloat162float(hi));
    }
}

__global__ void k_deg(const int* __restrict__ dst) {
    int e = blockIdx.x * blockDim.x + threadIdx.x;
    if (e < NE) atomicAdd(&g_deg[dst[e]], 1);
}

#define SCAN_CH 512
#define SCAN_NB 196  // ceil(100000/512)

__global__ void k_scan_partial() {
    __shared__ int sh[SCAN_CH];
    int b = blockIdx.x, t = threadIdx.x;
    int i = b * SCAN_CH + t;
    sh[t] = (i < NN) ? g_deg[i] : 0;
    for (int s = SCAN_CH / 2; s > 0; s >>= 1) {
        __syncthreads();
        if (t < s) sh[t] += sh[t + s];
    }
    if (t == 0) g_bsum[b] = sh[0];
}

__global__ void k_scan_top() {
    __shared__ int sh[256];
    int t = threadIdx.x;
    int v = (t < SCAN_NB) ? g_bsum[t] : 0;
    sh[t] = v;
    __syncthreads();
    for (int off = 1; off < 256; off <<= 1) {
        int a = (t >= off) ? sh[t - off] : 0;
        __syncthreads();
        sh[t] += a;
        __syncthreads();
    }
    g_boff[t] = sh[t] - v;  // exclusive
    if (t == 0) g_rowptr[NN] = NE;
}

__global__ void k_scan_apply() {
    __shared__ int sh[SCAN_CH];
    int b = blockIdx.x, t = threadIdx.x;
    int i = b * SCAN_CH + t;
    int v = (i < NN) ? g_deg[i] : 0;
    sh[t] = v;
    __syncthreads();
    for (int off = 1; off < SCAN_CH; off <<= 1) {
        int a = (t >= off) ? sh[t - off] : 0;
        __syncthreads();
        sh[t] += a;
        __syncthreads();
    }
    if (i < NN) g_rowptr[i] = g_boff[b] + sh[t] - v;  // exclusive global prefix
}

__global__ void k_fill(const int* __restrict__ src, const int* __restrict__ dst) {
    int e = blockIdx.x * blockDim.x + threadIdx.x;
    if (e >= NE) return;
    int d = dst[e];
    int pos = g_rowptr[d] + atomicAdd(&g_cursor[d], 1);
    g_csrsrc[pos] = src[e];
}

// ---------------------------------------------------------------------------
// Aggregation: warp per node, float4 per lane, gather-only
// ---------------------------------------------------------------------------
__global__ void __launch_bounds__(256) k_agg() {
    int w = blockIdx.x * 8 + (threadIdx.x >> 5);
    if (w >= NN) return;
    int lane = threadIdx.x & 31;
    int beg = g_rowptr[w], end = g_rowptr[w + 1];
    float4 acc = make_float4(0.f, 0.f, 0.f, 0.f);
    for (int e = beg; e < end; e++) {
        int s = g_csrsrc[e];
        float4 v = reinterpret_cast<const float4*>(g_h + (size_t)s * HD)[lane];
        acc.x += v.x; acc.y += v.y; acc.z += v.z; acc.w += v.w;
    }
    int cnt = end - beg;
    float inv = 1.0f / (float)(cnt > 0 ? cnt : 1);
    float vv[4] = {acc.x * inv, acc.y * inv, acc.z * inv, acc.w * inv};
    size_t o = (size_t)w * 256 + lane * 4;
#pragma unroll
    for (int j = 0; j < 4; j++) {
        __nv_bfloat16 hi = __float2bfloat16(vv[j]);
        g_Ahi[o + j] = hi;
        g_Alo[o + j] = __float2bfloat16(vv[j] - __bfloat162float(hi));
    }
}

// ---------------------------------------------------------------------------
// GEMM core: 256 threads, CTA tile 128(M) x 128(N), K chunks of 64 staged in
// swizzled smem. Warp tile 64x32 (2x4 warp grid). bf16 hi/lo 3-term split.
// SMEM layout: AHI 0, ALO 16K, BHI 32K, BLO 48K  (total 64KB dynamic)
// ---------------------------------------------------------------------------
#define SM_AHI 0
#define SM_ALO 16384
#define SM_BHI 32768
#define SM_BLO 49152
#define SM_BYTES 65536

struct Frags {
    float acc[4][4][4];
};

__device__ __forceinline__ void gemm_chunk_compute(uint32_t sb, int wid, int lane,
                                                   float acc[4][4][4]) {
    int m_base = (wid >> 2) * 64;
    int n_base = (wid & 3) * 32;
#pragma unroll
    for (int ks = 0; ks < 4; ks++) {
        uint32_t a_hi[4][4], a_lo[4][4];
#pragma unroll
        for (int mt = 0; mt < 4; mt++) {
            int row = m_base + mt * 16 + (lane & 15);
            int col = ks * 16 + ((lane >> 4) << 3);
            uint32_t ad = sb + SM_AHI + swz((uint32_t)(row * 128 + col * 2));
            ldsm4(a_hi[mt], ad);
            ldsm4(a_lo[mt], ad + (SM_ALO - SM_AHI));
        }
        uint32_t b_hi[2][4], b_lo[2][4];
#pragma unroll
        for (int nt2 = 0; nt2 < 2; nt2++) {
            int nrow = n_base + nt2 * 16 + (lane & 7) + (((lane >> 4) & 1) << 3);
            int col = ks * 16 + (((lane >> 3) & 1) << 3);
            uint32_t bd = sb + SM_BHI + swz((uint32_t)(nrow * 128 + col * 2));
            ldsm4(b_hi[nt2], bd);
            ldsm4(b_lo[nt2], bd + (SM_BLO - SM_BHI));
        }
#pragma unroll
        for (int mt = 0; mt < 4; mt++) {
#pragma unroll
            for (int nt = 0; nt < 4; nt++) {
                const uint32_t* bh = &b_hi[nt >> 1][(nt & 1) * 2];
                const uint32_t* bl = &b_lo[nt >> 1][(nt & 1) * 2];
                mma_bf16(acc[mt][nt], a_hi[mt], bh);
                mma_bf16(acc[mt][nt], a_lo[mt], bh);
                mma_bf16(acc[mt][nt], a_hi[mt], bl);
            }
        }
    }
}

// Layer GEMM: A = g_A(hi/lo) full 256 cols (mean||self), B = g_B(hi/lo)[layer],
// epilogue: bias + relu -> g_h, g_Ahi/g_Alo self halves.
__global__ void __launch_bounds__(256) k_layer_gemm(const float* __restrict__ bias, int layer) {
    extern __shared__ __align__(1024) char smem[];
    uint32_t sb = smem_to_u32(smem);
    int tid = threadIdx.x, wid = tid >> 5, lane = tid & 31;
    int base = blockIdx.x * 128;

    const __nv_bfloat16* Bh = g_Bhi + (size_t)layer * HD * 256;
    const __nv_bfloat16* Bl = g_Blo + (size_t)layer * HD * 256;

    float acc[4][4][4];
#pragma unroll
    for (int i = 0; i < 4; i++)
#pragma unroll
        for (int j = 0; j < 4; j++)
#pragma unroll
            for (int q = 0; q < 4; q++) acc[i][j][q] = 0.f;

    for (int kc = 0; kc < 4; kc++) {
        int k0 = kc * 64;
        if (kc) __syncthreads();  // protect previous chunk's reads
        for (int idx = tid; idx < 1024; idx += 256) {
            int r = idx >> 3, s = idx & 7;
            int node = base + r; if (node >= NN) node = NN - 1;
            size_t ga = (size_t)node * 256 + k0 + s * 8;
            size_t gb = (size_t)r * 256 + k0 + s * 8;
            uint32_t so = swz((uint32_t)(r * 128 + s * 16));
            *reinterpret_cast<uint4*>(smem + SM_AHI + so) = *reinterpret_cast<const uint4*>(g_Ahi + ga);
            *reinterpret_cast<uint4*>(smem + SM_ALO + so) = *reinterpret_cast<const uint4*>(g_Alo + ga);
            *reinterpret_cast<uint4*>(smem + SM_BHI + so) = *reinterpret_cast<const uint4*>(Bh + gb);
            *reinterpret_cast<uint4*>(smem + SM_BLO + so) = *reinterpret_cast<const uint4*>(Bl + gb);
        }
        __syncthreads();
        gemm_chunk_compute(sb, wid, lane, acc);
    }

    // Epilogue: bias + relu, write fp32 + hi/lo bf16 self features
    int gid = lane >> 2, itg = lane & 3;
    int m_base = (wid >> 2) * 64, n_base = (wid & 3) * 32;
#pragma unroll
    for (int mt = 0; mt < 4; mt++) {
#pragma unroll
        for (int nt = 0; nt < 4; nt++) {
            int col = n_base + nt * 8 + itg * 2;
            float b0 = bias[col], b1 = bias[col + 1];
#pragma unroll
            for (int half = 0; half < 2; half++) {
                int node = base + m_base + mt * 16 + gid + half * 8;
                if (node >= NN) continue;
                float v0 = acc[mt][nt][half * 2 + 0] + b0;
                float v1 = acc[mt][nt][half * 2 + 1] + b1;
                v0 = v0 > 0.f ? v0 : 0.f;
                v1 = v1 > 0.f ? v1 : 0.f;
                *reinterpret_cast<float2*>(g_h + (size_t)node * HD + col) = make_float2(v0, v1);
                __nv_bfloat16 h0 = __float2bfloat16(v0), h1 = __float2bfloat16(v1);
                __nv_bfloat16 l0 = __float2bfloat16(v0 - __bfloat162float(h0));
                __nv_bfloat16 l1 = __float2bfloat16(v1 - __bfloat162float(h1));
                size_t o = (size_t)node * 256 + 128 + col;
                *reinterpret_cast<__nv_bfloat162*>(&g_Ahi[o]) = __nv_bfloat162{h0, h1};
                *reinterpret_cast<__nv_bfloat162*>(&g_Alo[o]) = __nv_bfloat162{l0, l1};
            }
        }
    }
}

// Final GEMM: logits tile 128(M) x 128(N of vocab), K = 128 (self features),
// epilogue: + blast, write to d_out (cols < 1000).
__global__ void __launch_bounds__(256) k_final_gemm(const float* __restrict__ blast,
                                                    float* __restrict__ out) {
    extern __shared__ __align__(1024) char smem[];
    uint32_t sb = smem_to_u32(smem);
    int tid = threadIdx.x, wid = tid >> 5, lane = tid & 31;
    int base = blockIdx.x * 128;
    int ncol0 = blockIdx.y * 128;

    float acc[4][4][4];
#pragma unroll
    for (int i = 0; i < 4; i++)
#pragma unroll
        for (int j = 0; j < 4; j++)
#pragma unroll
            for (int q = 0; q < 4; q++) acc[i][j][q] = 0.f;

    for (int kc = 0; kc < 2; kc++) {
        int k0 = kc * 64;
        if (kc) __syncthreads();
        for (int idx = tid; idx < 1024; idx += 256) {
            int r = idx >> 3, s = idx & 7;
            int node = base + r; if (node >= NN) node = NN - 1;
            size_t ga = (size_t)node * 256 + 128 + k0 + s * 8;
            size_t gb = (size_t)(ncol0 + r) * HD + k0 + s * 8;
            uint32_t so = swz((uint32_t)(r * 128 + s * 16));
            *reinterpret_cast<uint4*>(smem + SM_AHI + so) = *reinterpret_cast<const uint4*>(g_Ahi + ga);
            *reinterpret_cast<uint4*>(smem + SM_ALO + so) = *reinterpret_cast<const uint4*>(g_Alo + ga);
            *reinterpret_cast<uint4*>(smem + SM_BHI + so) = *reinterpret_cast<const uint4*>(g_BLhi + gb);
            *reinterpret_cast<uint4*>(smem + SM_BLO + so) = *reinterpret_cast<const uint4*>(g_BLlo + gb);
        }
        __syncthreads();
        gemm_chunk_compute(sb, wid, lane, acc);
    }

    int gid = lane >> 2, itg = lane & 3;
    int m_base = (wid >> 2) * 64, n_base = (wid & 3) * 32;
#pragma unroll
    for (int mt = 0; mt < 4; mt++) {
#pragma unroll
        for (int nt = 0; nt < 4; nt++) {
            int col = ncol0 + n_base + nt * 8 + itg * 2;
            if (col >= VC) continue;
            float b0 = blast[col];
            float b1 = (col + 1 < VC) ? blast[col + 1] : 0.f;
#pragma unroll
            for (int half = 0; half < 2; half++) {
                int node = base + m_base + mt * 16 + gid + half * 8;
                if (node >= NN) continue;
                float v0 = acc[mt][nt][half * 2 + 0] + b0;
                float v1 = acc[mt][nt][half * 2 + 1] + b1;
                size_t o = (size_t)node * VC + col;
                out[o] = v0;
                if (col + 1 < VC) out[o + 1] = v1;
            }
        }
    }
}

// ---------------------------------------------------------------------------
// Softmax: warp per row, 1000 cols held in registers (32 per lane)
// ---------------------------------------------------------------------------
__global__ void __launch_bounds__(256) k_softmax(float* __restrict__ out) {
    int w = blockIdx.x * 8 + (threadIdx.x >> 5);
    if (w >= NN) return;
    int lane = threadIdx.x & 31;
    float r[32];
    float mx = -1e30f;
    float* row = out + (size_t)w * VC;
#pragma unroll
    for (int i = 0; i < 32; i++) {
        int c = lane + i * 32;
        float v = (c < VC) ? row[c] : -1e30f;
        r[i] = v;
        mx = fmaxf(mx, v);
    }
#pragma unroll
    for (int o = 16; o > 0; o >>= 1) mx = fmaxf(mx, __shfl_xor_sync(0xFFFFFFFF, mx, o));
    float sum = 0.f;
#pragma unroll
    for (int i = 0; i < 32; i++) {
        int c = lane + i * 32;
        if (c < VC) { r[i] = __expf(r[i] - mx); sum += r[i]; }
    }
#pragma unroll
    for (int o = 16; o > 0; o >>= 1) sum += __shfl_xor_sync(0xFFFFFFFF, sum, o);
    float inv = 1.0f / sum;
#pragma unroll
    for (int i = 0; i < 32; i++) {
        int c = lane + i * 32;
        if (c < VC) row[c] = r[i] * inv;
    }
}

// ---------------------------------------------------------------------------
// Launch
// ---------------------------------------------------------------------------
extern "C" void kernel_launch(void* const* d_in, const int* in_sizes, int n_in,
                              void* d_out, int out_size) {
    const int*   x     = (const int*)d_in[0];
    const int*   ei    = (const int*)d_in[1];
    const float* emb   = (const float*)d_in[2];
    const float* Wl    = (const float*)d_in[3];
    const float* bl    = (const float*)d_in[4];
    const float* Wr    = (const float*)d_in[5];
    const float* Wlast = (const float*)d_in[6];
    const float* blast = (const float*)d_in[7];
    float* out = (float*)d_out;
    const int* src = ei;
    const int* dst = ei + NE;

    cudaFuncSetAttribute(k_layer_gemm, cudaFuncAttributeMaxDynamicSharedMemorySize, SM_BYTES);
    cudaFuncSetAttribute(k_final_gemm, cudaFuncAttributeMaxDynamicSharedMemorySize, SM_BYTES);

    k_zero<<<(NN + 255) / 256, 256>>>();
    k_embed<<<(NN * 32 + 255) / 256, 256>>>(x, emb);
    k_prep_w<<<(NL * HD * 2 * HD + VP * HD + 255) / 256, 256>>>(Wl, Wr, Wlast);
    k_deg<<<(NE + 255) / 256, 256>>>(dst);
    k_scan_partial<<<SCAN_NB, SCAN_CH>>>();
    k_scan_top<<<1, 256>>>();
    k_scan_apply<<<SCAN_NB, SCAN_CH>>>();
    k_fill<<<(NE + 255) / 256, 256>>>(src, dst);

    int nb = (NN + 127) / 128;
    for (int l = 0; l < NL; l++) {
        k_agg<<<(NN + 7) / 8, 256>>>();
        k_layer_gemm<<<nb, 256, SM_BYTES>>>(bl + l * HD, l);
    }

    dim3 fgrid(nb, VP / 128);
    k_final_gemm<<<fgrid, 256, SM_BYTES>>>(blast, out);
    k_softmax<<<(NN + 7) / 8, 256>>>(out);
}

// round 9
// speedup vs baseline: 1.3327x; 1.0083x over previous
#include <cuda_runtime.h>
#include <cuda_bf16.h>
#include <cstdint>
#include <cstddef>

#define NN 100000
#define NE 1600000
#define HD 128
#define VC 1000
#define VP 1024
#define NL 3

// ---------------------------------------------------------------------------
// Device scratch (static __device__ arrays; no allocations allowed)
// ---------------------------------------------------------------------------
__device__ __align__(256) float         g_h[(size_t)NN * HD];        // fp32 node features
__device__ __align__(256) __nv_bfloat16 g_Ahi[(size_t)NN * 2 * HD];  // [N,256]: cols 0..127 = mean, 128..255 = self (hi)
__device__ __align__(256) __nv_bfloat16 g_Alo[(size_t)NN * 2 * HD];  // lo parts
__device__ __align__(256) __nv_bfloat16 g_Bhi[NL * HD * 2 * HD];     // [l][n][k] combined [Wl;Wr]^T, K-major, hi
__device__ __align__(256) __nv_bfloat16 g_Blo[NL * HD * 2 * HD];
__device__ __align__(256) __nv_bfloat16 g_BLhi[VP * HD];             // [n][k] Wlast^T (n padded to 1024), hi
__device__ __align__(256) __nv_bfloat16 g_BLlo[VP * HD];
__device__ int g_deg[NN];
__device__ int g_cursor[NN];
__device__ int g_rowptr[NN + 1];
__device__ int g_csrsrc[NE];
__device__ int g_bsum[256];
__device__ int g_boff[256];

// ---------------------------------------------------------------------------
// HMMA helpers (sm_80 baseline features only -- target is sm_103 non-'a')
// ---------------------------------------------------------------------------
__device__ __forceinline__ uint32_t smem_to_u32(const void* p) {
    uint32_t a;
    asm("{ .reg .u64 t; cvta.to.shared.u64 t, %1; cvt.u32.u64 %0, t; }" : "=r"(a) : "l"(p));
    return a;
}
__device__ __forceinline__ uint32_t swz(uint32_t o) { return o ^ ((o >> 3) & 0x70); }

__device__ __forceinline__ void ldsm4(uint32_t* r, uint32_t addr) {
    asm volatile("ldmatrix.sync.aligned.m8n8.x4.shared.b16 {%0,%1,%2,%3}, [%4];"
                 : "=r"(r[0]), "=r"(r[1]), "=r"(r[2]), "=r"(r[3]) : "r"(addr));
}
__device__ __forceinline__ void mma_bf16(float* d, const uint32_t* a, const uint32_t* b) {
    asm volatile(
        "mma.sync.aligned.m16n8k16.row.col.f32.bf16.bf16.f32 "
        "{%0,%1,%2,%3}, {%4,%5,%6,%7}, {%8,%9}, {%0,%1,%2,%3};"
        : "+f"(d[0]), "+f"(d[1]), "+f"(d[2]), "+f"(d[3])
        : "r"(a[0]), "r"(a[1]), "r"(a[2]), "r"(a[3]), "r"(b[0]), "r"(b[1]));
}

// ---------------------------------------------------------------------------
// Small kernels: init / embed / weight prep / CSR build
// ---------------------------------------------------------------------------
__global__ void k_zero() {
    int i = blockIdx.x * blockDim.x + threadIdx.x;
    if (i < NN) { g_deg[i] = 0; g_cursor[i] = 0; }
}

__global__ void k_embed(const int* __restrict__ x, const float* __restrict__ emb) {
    int idx = blockIdx.x * blockDim.x + threadIdx.x;  // NN*32 threads, float4 each
    if (idx >= NN * 32) return;
    int n = idx >> 5, q = idx & 31;
    float4 v = reinterpret_cast<const float4*>(emb + (size_t)x[n] * HD)[q];
    reinterpret_cast<float4*>(g_h + (size_t)n * HD)[q] = v;
    size_t o = (size_t)n * 256 + 128 + q * 4;
    float vv[4] = {v.x, v.y, v.z, v.w};
#pragma unroll
    for (int j = 0; j < 4; j++) {
        __nv_bfloat16 hi = __float2bfloat16(vv[j]);
        g_Ahi[o + j] = hi;
        g_Alo[o + j] = __float2bfloat16(vv[j] - __bfloat162float(hi));
    }
}

__global__ void k_prep_w(const float* __restrict__ Wl, const float* __restrict__ Wr,
                         const float* __restrict__ Wlast) {
    int idx = blockIdx.x * blockDim.x + threadIdx.x;
    if (idx < NL * HD * 2 * HD) {  // [l][n][k], k in 0..255
        int l = idx / (HD * 2 * HD);
        int rem = idx % (HD * 2 * HD);
        int n = rem / 256, k = rem % 256;
        float w = (k < HD) ? Wl[l * HD * HD + k * HD + n] : Wr[l * HD * HD + (k - HD) * HD + n];
        __nv_bfloat16 hi = __float2bfloat16(w);
        g_Bhi[idx] = hi;
        g_Blo[idx] = __float2bfloat16(w - __bfloat162float(hi));
    } else {
        int i2 = idx - NL * HD * 2 * HD;
        if (i2 >= VP * HD) return;
        int n = i2 / HD, k = i2 % HD;
        float w = (n < VC) ? Wlast[(size_t)k * VC + n] : 0.0f;
        __nv_bfloat16 hi = __float2bfloat16(w);
        g_BLhi[i2] = hi;
        g_BLlo[i2] = __float2bfloat16(w - __bfloat162float(hi));
    }
}

__global__ void k_deg(const int* __restrict__ dst) {
    int e = blockIdx.x * blockDim.x + threadIdx.x;
    if (e < NE) atomicAdd(&g_deg[dst[e]], 1);
}

#define SCAN_CH 512
#define SCAN_NB 196  // ceil(100000/512)

__global__ void k_scan_partial() {
    __shared__ int sh[SCAN_CH];
    int b = blockIdx.x, t = threadIdx.x;
    int i = b * SCAN_CH + t;
    sh[t] = (i < NN) ? g_deg[i] : 0;
    for (int s = SCAN_CH / 2; s > 0; s >>= 1) {
        __syncthreads();
        if (t < s) sh[t] += sh[t + s];
    }
    if (t == 0) g_bsum[b] = sh[0];
}

__global__ void k_scan_top() {
    __shared__ int sh[256];
    int t = threadIdx.x;
    int v = (t < SCAN_NB) ? g_bsum[t] : 0;
    sh[t] = v;
    __syncthreads();
    for (int off = 1; off < 256; off <<= 1) {
        int a = (t >= off) ? sh[t - off] : 0;
        __syncthreads();
        sh[t] += a;
        __syncthreads();
    }
    g_boff[t] = sh[t] - v;  // exclusive
    if (t == 0) g_rowptr[NN] = NE;
}

__global__ void k_scan_apply() {
    __shared__ int sh[SCAN_CH];
    int b = blockIdx.x, t = threadIdx.x;
    int i = b * SCAN_CH + t;
    int v = (i < NN) ? g_deg[i] : 0;
    sh[t] = v;
    __syncthreads();
    for (int off = 1; off < SCAN_CH; off <<= 1) {
        int a = (t >= off) ? sh[t - off] : 0;
        __syncthreads();
        sh[t] += a;
        __syncthreads();
    }
    if (i < NN) g_rowptr[i] = g_boff[b] + sh[t] - v;  // exclusive global prefix
}

__global__ void k_fill(const int* __restrict__ src, const int* __restrict__ dst) {
    int e = blockIdx.x * blockDim.x + threadIdx.x;
    if (e >= NE) return;
    int d = dst[e];
    int pos = g_rowptr[d] + atomicAdd(&g_cursor[d], 1);
    g_csrsrc[pos] = src[e];
}

// ---------------------------------------------------------------------------
// Aggregation: warp per node, float4 per lane, gather-only
// ---------------------------------------------------------------------------
__global__ void __launch_bounds__(256) k_agg() {
    int w = blockIdx.x * 8 + (threadIdx.x >> 5);
    if (w >= NN) return;
    int lane = threadIdx.x & 31;
    int beg = g_rowptr[w], end = g_rowptr[w + 1];
    float4 acc = make_float4(0.f, 0.f, 0.f, 0.f);
    for (int e = beg; e < end; e++) {
        int s = g_csrsrc[e];
        float4 v = reinterpret_cast<const float4*>(g_h + (size_t)s * HD)[lane];
        acc.x += v.x; acc.y += v.y; acc.z += v.z; acc.w += v.w;
    }
    int cnt = end - beg;
    float inv = 1.0f / (float)(cnt > 0 ? cnt : 1);
    float vv[4] = {acc.x * inv, acc.y * inv, acc.z * inv, acc.w * inv};
    size_t o = (size_t)w * 256 + lane * 4;
#pragma unroll
    for (int j = 0; j < 4; j++) {
        __nv_bfloat16 hi = __float2bfloat16(vv[j]);
        g_Ahi[o + j] = hi;
        g_Alo[o + j] = __float2bfloat16(vv[j] - __bfloat162float(hi));
    }
}

// ---------------------------------------------------------------------------
// GEMM core: 256 threads, CTA tile 128(M) x 128(N), K chunks of 64 staged in
// swizzled smem. Warp tile 64x32 (2x4 warp grid). bf16 hi/lo 3-term split.
// SMEM layout: AHI 0, ALO 16K, BHI 32K, BLO 48K  (total 64KB dynamic)
// ---------------------------------------------------------------------------
#define SM_AHI 0
#define SM_ALO 16384
#define SM_BHI 32768
#define SM_BLO 49152
#define SM_BYTES 65536

struct Frags {
    float acc[4][4][4];
};

__device__ __forceinline__ void gemm_chunk_compute(uint32_t sb, int wid, int lane,
                                                   float acc[4][4][4]) {
    int m_base = (wid >> 2) * 64;
    int n_base = (wid & 3) * 32;
#pragma unroll
    for (int ks = 0; ks < 4; ks++) {
        uint32_t a_hi[4][4], a_lo[4][4];
#pragma unroll
        for (int mt = 0; mt < 4; mt++) {
            int row = m_base + mt * 16 + (lane & 15);
            int col = ks * 16 + ((lane >> 4) << 3);
            uint32_t ad = sb + SM_AHI + swz((uint32_t)(row * 128 + col * 2));
            ldsm4(a_hi[mt], ad);
            ldsm4(a_lo[mt], ad + (SM_ALO - SM_AHI));
        }
        uint32_t b_hi[2][4], b_lo[2][4];
#pragma unroll
        for (int nt2 = 0; nt2 < 2; nt2++) {
            int nrow = n_base + nt2 * 16 + (lane & 7) + (((lane >> 4) & 1) << 3);
            int col = ks * 16 + (((lane >> 3) & 1) << 3);
            uint32_t bd = sb + SM_BHI + swz((uint32_t)(nrow * 128 + col * 2));
            ldsm4(b_hi[nt2], bd);
            ldsm4(b_lo[nt2], bd + (SM_BLO - SM_BHI));
        }
#pragma unroll
        for (int mt = 0; mt < 4; mt++) {
#pragma unroll
            for (int nt = 0; nt < 4; nt++) {
                const uint32_t* bh = &b_hi[nt >> 1][(nt & 1) * 2];
                const uint32_t* bl = &b_lo[nt >> 1][(nt & 1) * 2];
                mma_bf16(acc[mt][nt], a_hi[mt], bh);
                mma_bf16(acc[mt][nt], a_lo[mt], bh);
                mma_bf16(acc[mt][nt], a_hi[mt], bl);
            }
        }
    }
}

// Layer GEMM: A = g_A(hi/lo) full 256 cols (mean||self), B = g_B(hi/lo)[layer],
// epilogue: bias + relu -> g_h, g_Ahi/g_Alo self halves.
__global__ void __launch_bounds__(256) k_layer_gemm(const float* __restrict__ bias, int layer) {
    extern __shared__ __align__(1024) char smem[];
    uint32_t sb = smem_to_u32(smem);
    int tid = threadIdx.x, wid = tid >> 5, lane = tid & 31;
    int base = blockIdx.x * 128;

    const __nv_bfloat16* Bh = g_Bhi + (size_t)layer * HD * 256;
    const __nv_bfloat16* Bl = g_Blo + (size_t)layer * HD * 256;

    float acc[4][4][4];
#pragma unroll
    for (int i = 0; i < 4; i++)
#pragma unroll
        for (int j = 0; j < 4; j++)
#pragma unroll
            for (int q = 0; q < 4; q++) acc[i][j][q] = 0.f;

    for (int kc = 0; kc < 4; kc++) {
        int k0 = kc * 64;
        if (kc) __syncthreads();  // protect previous chunk's reads
        for (int idx = tid; idx < 1024; idx += 256) {
            int r = idx >> 3, s = idx & 7;
            int node = base + r; if (node >= NN) node = NN - 1;
            size_t ga = (size_t)node * 256 + k0 + s * 8;
            size_t gb = (size_t)r * 256 + k0 + s * 8;
            uint32_t so = swz((uint32_t)(r * 128 + s * 16));
            *reinterpret_cast<uint4*>(smem + SM_AHI + so) = *reinterpret_cast<const uint4*>(g_Ahi + ga);
            *reinterpret_cast<uint4*>(smem + SM_ALO + so) = *reinterpret_cast<const uint4*>(g_Alo + ga);
            *reinterpret_cast<uint4*>(smem + SM_BHI + so) = *reinterpret_cast<const uint4*>(Bh + gb);
            *reinterpret_cast<uint4*>(smem + SM_BLO + so) = *reinterpret_cast<const uint4*>(Bl + gb);
        }
        __syncthreads();
        gemm_chunk_compute(sb, wid, lane, acc);
    }

    // Epilogue: bias + relu, write fp32 + hi/lo bf16 self features
    int gid = lane >> 2, itg = lane & 3;
    int m_base = (wid >> 2) * 64, n_base = (wid & 3) * 32;
#pragma unroll
    for (int mt = 0; mt < 4; mt++) {
#pragma unroll
        for (int nt = 0; nt < 4; nt++) {
            int col = n_base + nt * 8 + itg * 2;
            float b0 = bias[col], b1 = bias[col + 1];
#pragma unroll
            for (int half = 0; half < 2; half++) {
                int node = base + m_base + mt * 16 + gid + half * 8;
                if (node >= NN) continue;
                float v0 = acc[mt][nt][half * 2 + 0] + b0;
                float v1 = acc[mt][nt][half * 2 + 1] + b1;
                v0 = v0 > 0.f ? v0 : 0.f;
                v1 = v1 > 0.f ? v1 : 0.f;
                *reinterpret_cast<float2*>(g_h + (size_t)node * HD + col) = make_float2(v0, v1);
                __nv_bfloat16 h0 = __float2bfloat16(v0), h1 = __float2bfloat16(v1);
                __nv_bfloat16 l0 = __float2bfloat16(v0 - __bfloat162float(h0));
                __nv_bfloat16 l1 = __float2bfloat16(v1 - __bfloat162float(h1));
                size_t o = (size_t)node * 256 + 128 + col;
                *reinterpret_cast<__nv_bfloat162*>(&g_Ahi[o]) = __nv_bfloat162{h0, h1};
                *reinterpret_cast<__nv_bfloat162*>(&g_Alo[o]) = __nv_bfloat162{l0, l1};
            }
        }
    }
}

// Final GEMM: logits tile 128(M) x 128(N of vocab), K = 128 (self features),
// epilogue: + blast, write to d_out (cols < 1000).
__global__ void __launch_bounds__(256) k_final_gemm(const float* __restrict__ blast,
                                                    float* __restrict__ out) {
    extern __shared__ __align__(1024) char smem[];
    uint32_t sb = smem_to_u32(smem);
    int tid = threadIdx.x, wid = tid >> 5, lane = tid & 31;
    int base = blockIdx.x * 128;
    int ncol0 = blockIdx.y * 128;

    float acc[4][4][4];
#pragma unroll
    for (int i = 0; i < 4; i++)
#pragma unroll
        for (int j = 0; j < 4; j++)
#pragma unroll
            for (int q = 0; q < 4; q++) acc[i][j][q] = 0.f;

    for (int kc = 0; kc < 2; kc++) {
        int k0 = kc * 64;
        if (kc) __syncthreads();
        for (int idx = tid; idx < 1024; idx += 256) {
            int r = idx >> 3, s = idx & 7;
            int node = base + r; if (node >= NN) node = NN - 1;
            size_t ga = (size_t)node * 256 + 128 + k0 + s * 8;
            size_t gb = (size_t)(ncol0 + r) * HD + k0 + s * 8;
            uint32_t so = swz((uint32_t)(r * 128 + s * 16));
            *reinterpret_cast<uint4*>(smem + SM_AHI + so) = *reinterpret_cast<const uint4*>(g_Ahi + ga);
            *reinterpret_cast<uint4*>(smem + SM_ALO + so) = *reinterpret_cast<const uint4*>(g_Alo + ga);
            *reinterpret_cast<uint4*>(smem + SM_BHI + so) = *reinterpret_cast<const uint4*>(g_BLhi + gb);
            *reinterpret_cast<uint4*>(smem + SM_BLO + so) = *reinterpret_cast<const uint4*>(g_BLlo + gb);
        }
        __syncthreads();
        gemm_chunk_compute(sb, wid, lane, acc);
    }

    int gid = lane >> 2, itg = lane & 3;
    int m_base = (wid >> 2) * 64, n_base = (wid & 3) * 32;
#pragma unroll
    for (int mt = 0; mt < 4; mt++) {
#pragma unroll
        for (int nt = 0; nt < 4; nt++) {
            int col = ncol0 + n_base + nt * 8 + itg * 2;
            if (col >= VC) continue;
            float b0 = blast[col];
            float b1 = (col + 1 < VC) ? blast[col + 1] : 0.f;
#pragma unroll
            for (int half = 0; half < 2; half++) {
                int node = base + m_base + mt * 16 + gid + half * 8;
                if (node >= NN) continue;
                float v0 = acc[mt][nt][half * 2 + 0] + b0;
                float v1 = acc[mt][nt][half * 2 + 1] + b1;
                size_t o = (size_t)node * VC + col;
                out[o] = v0;
                if (col + 1 < VC) out[o + 1] = v1;
            }
        }
    }
}

// ---------------------------------------------------------------------------
// Softmax: warp per row, 1000 cols held in registers (32 per lane)
// ---------------------------------------------------------------------------
__global__ void __launch_bounds__(256) k_softmax(float* __restrict__ out) {
    int w = blockIdx.x * 8 + (threadIdx.x >> 5);
    if (w >= NN) return;
    int lane = threadIdx.x & 31;
    float r[32];
    float mx = -1e30f;
    float* row = out + (size_t)w * VC;
#pragma unroll
    for (int i = 0; i < 32; i++) {
        int c = lane + i * 32;
        float v = (c < VC) ? row[c] : -1e30f;
        r[i] = v;
        mx = fmaxf(mx, v);
    }
#pragma unroll
    for (int o = 16; o > 0; o >>= 1) mx = fmaxf(mx, __shfl_xor_sync(0xFFFFFFFF, mx, o));
    float sum = 0.f;
#pragma unroll
    for (int i = 0; i < 32; i++) {
        int c = lane + i * 32;
        if (c < VC) { r[i] = __expf(r[i] - mx); sum += r[i]; }
    }
#pragma unroll
    for (int o = 16; o > 0; o >>= 1) sum += __shfl_xor_sync(0xFFFFFFFF, sum, o);
    float inv = 1.0f / sum;
#pragma unroll
    for (int i = 0; i < 32; i++) {
        int c = lane + i * 32;
        if (c < VC) row[c] = r[i] * inv;
    }
}

// ---------------------------------------------------------------------------
// Launch
// ---------------------------------------------------------------------------
extern "C" void kernel_launch(void* const* d_in, const int* in_sizes, int n_in,
                              void* d_out, int out_size) {
    const int*   x     = (const int*)d_in[0];
    const int*   ei    = (const int*)d_in[1];
    const float* emb   = (const float*)d_in[2];
    const float* Wl    = (const float*)d_in[3];
    const float* bl    = (const float*)d_in[4];
    const float* Wr    = (const float*)d_in[5];
    const float* Wlast = (const float*)d_in[6];
    const float* blast = (const float*)d_in[7];
    float* out = (float*)d_out;
    const int* src = ei;
    const int* dst = ei + NE;

    cudaFuncSetAttribute(k_layer_gemm, cudaFuncAttributeMaxDynamicSharedMemorySize, SM_BYTES);
    cudaFuncSetAttribute(k_final_gemm, cudaFuncAttributeMaxDynamicSharedMemorySize, SM_BYTES);

    k_zero<<<(NN + 255) / 256, 256>>>();
    k_embed<<<(NN * 32 + 255) / 256, 256>>>(x, emb);
    k_prep_w<<<(NL * HD * 2 * HD + VP * HD + 255) / 256, 256>>>(Wl, Wr, Wlast);
    k_deg<<<(NE + 255) / 256, 256>>>(dst);
    k_scan_partial<<<SCAN_NB, SCAN_CH>>>();
    k_scan_top<<<1, 256>>>();
    k_scan_apply<<<SCAN_NB, SCAN_CH>>>();
    k_fill<<<(NE + 255) / 256, 256>>>(src, dst);

    int nb = (NN + 127) / 128;
    for (int l = 0; l < NL; l++) {
        k_agg<<<(NN + 7) / 8, 256>>>();
        k_layer_gemm<<<nb, 256, SM_BYTES>>>(bl + l * HD, l);
    }

    dim3 fgrid(nb, VP / 128);
    k_final_gemm<<<fgrid, 256, SM_BYTES>>>(blast, out);
    k_softmax<<<(NN + 7) / 8, 256>>>(out);
}

// round 10
// speedup vs baseline: 1.3361x; 1.0026x over previous
#include <cuda_runtime.h>
#include <cuda_bf16.h>
#include <cstdint>
#include <cstddef>

#define NN 100000
#define NE 1600000
#define HD 128
#define VC 1000
#define VP 1024
#define NL 3

// ---------------------------------------------------------------------------
// Device scratch (static __device__ arrays; no allocations allowed)
// ---------------------------------------------------------------------------
__device__ __align__(256) float         g_h[(size_t)NN * HD];        // fp32 node features
__device__ __align__(256) __nv_bfloat16 g_Ahi[(size_t)NN * 2 * HD];  // [N,256]: cols 0..127 = mean, 128..255 = self (hi)
__device__ __align__(256) __nv_bfloat16 g_Alo[(size_t)NN * 2 * HD];  // lo parts
__device__ __align__(256) __nv_bfloat16 g_Bhi[NL * HD * 2 * HD];     // [l][n][k] combined [Wl;Wr]^T, K-major, hi
__device__ __align__(256) __nv_bfloat16 g_Blo[NL * HD * 2 * HD];
__device__ __align__(256) __nv_bfloat16 g_BLhi[VP * HD];             // [n][k] Wlast^T (n padded to 1024), hi
__device__ __align__(256) __nv_bfloat16 g_BLlo[VP * HD];
__device__ int g_deg[NN];
__device__ int g_cursor[NN];
__device__ int g_rowptr[NN + 1];
__device__ int g_csrsrc[NE];
__device__ int g_bsum[256];
__device__ int g_boff[256];

// ---------------------------------------------------------------------------
// HMMA helpers (sm_80 baseline features only -- target is sm_103 non-'a')
// ---------------------------------------------------------------------------
__device__ __forceinline__ uint32_t smem_to_u32(const void* p) {
    uint32_t a;
    asm("{ .reg .u64 t; cvta.to.shared.u64 t, %1; cvt.u32.u64 %0, t; }" : "=r"(a) : "l"(p));
    return a;
}
__device__ __forceinline__ uint32_t swz(uint32_t o) { return o ^ ((o >> 3) & 0x70); }

__device__ __forceinline__ void ldsm4(uint32_t* r, uint32_t addr) {
    asm volatile("ldmatrix.sync.aligned.m8n8.x4.shared.b16 {%0,%1,%2,%3}, [%4];"
                 : "=r"(r[0]), "=r"(r[1]), "=r"(r[2]), "=r"(r[3]) : "r"(addr));
}
__device__ __forceinline__ void mma_bf16(float* d, const uint32_t* a, const uint32_t* b) {
    asm volatile(
        "mma.sync.aligned.m16n8k16.row.col.f32.bf16.bf16.f32 "
        "{%0,%1,%2,%3}, {%4,%5,%6,%7}, {%8,%9}, {%0,%1,%2,%3};"
        : "+f"(d[0]), "+f"(d[1]), "+f"(d[2]), "+f"(d[3])
        : "r"(a[0]), "r"(a[1]), "r"(a[2]), "r"(a[3]), "r"(b[0]), "r"(b[1]));
}

// ---------------------------------------------------------------------------
// Small kernels: init / embed / weight prep / CSR build
// ---------------------------------------------------------------------------
__global__ void k_zero() {
    int i = blockIdx.x * blockDim.x + threadIdx.x;
    if (i < NN) { g_deg[i] = 0; g_cursor[i] = 0; }
}

__global__ void k_embed(const int* __restrict__ x, const float* __restrict__ emb) {
    int idx = blockIdx.x * blockDim.x + threadIdx.x;  // NN*32 threads, float4 each
    if (idx >= NN * 32) return;
    int n = idx >> 5, q = idx & 31;
    float4 v = reinterpret_cast<const float4*>(emb + (size_t)x[n] * HD)[q];
    reinterpret_cast<float4*>(g_h + (size_t)n * HD)[q] = v;
    size_t o = (size_t)n * 256 + 128 + q * 4;
    float vv[4] = {v.x, v.y, v.z, v.w};
#pragma unroll
    for (int j = 0; j < 4; j++) {
        __nv_bfloat16 hi = __float2bfloat16(vv[j]);
        g_Ahi[o + j] = hi;
        g_Alo[o + j] = __float2bfloat16(vv[j] - __bfloat162float(hi));
    }
}

__global__ void k_prep_w(const float* __restrict__ Wl, const float* __restrict__ Wr,
                         const float* __restrict__ Wlast) {
    int idx = blockIdx.x * blockDim.x + threadIdx.x;
    if (idx < NL * HD * 2 * HD) {  // [l][n][k], k in 0..255
        int l = idx / (HD * 2 * HD);
        int rem = idx % (HD * 2 * HD);
        int n = rem / 256, k = rem % 256;
        float w = (k < HD) ? Wl[l * HD * HD + k * HD + n] : Wr[l * HD * HD + (k - HD) * HD + n];
        __nv_bfloat16 hi = __float2bfloat16(w);
        g_Bhi[idx] = hi;
        g_Blo[idx] = __float2bfloat16(w - __bfloat162float(hi));
    } else {
        int i2 = idx - NL * HD * 2 * HD;
        if (i2 >= VP * HD) return;
        int n = i2 / HD, k = i2 % HD;
        float w = (n < VC) ? Wlast[(size_t)k * VC + n] : 0.0f;
        __nv_bfloat16 hi = __float2bfloat16(w);
        g_BLhi[i2] = hi;
        g_BLlo[i2] = __float2bfloat16(w - __bfloat162float(hi));
    }
}

__global__ void k_deg(const int* __restrict__ dst) {
    int e = blockIdx.x * blockDim.x + threadIdx.x;
    if (e < NE) atomicAdd(&g_deg[dst[e]], 1);
}

#define SCAN_CH 512
#define SCAN_NB 196  // ceil(100000/512)

__global__ void k_scan_partial() {
    __shared__ int sh[SCAN_CH];
    int b = blockIdx.x, t = threadIdx.x;
    int i = b * SCAN_CH + t;
    sh[t] = (i < NN) ? g_deg[i] : 0;
    for (int s = SCAN_CH / 2; s > 0; s >>= 1) {
        __syncthreads();
        if (t < s) sh[t] += sh[t + s];
    }
    if (t == 0) g_bsum[b] = sh[0];
}

__global__ void k_scan_top() {
    __shared__ int sh[256];
    int t = threadIdx.x;
    int v = (t < SCAN_NB) ? g_bsum[t] : 0;
    sh[t] = v;
    __syncthreads();
    for (int off = 1; off < 256; off <<= 1) {
        int a = (t >= off) ? sh[t - off] : 0;
        __syncthreads();
        sh[t] += a;
        __syncthreads();
    }
    g_boff[t] = sh[t] - v;  // exclusive
    if (t == 0) g_rowptr[NN] = NE;
}

__global__ void k_scan_apply() {
    __shared__ int sh[SCAN_CH];
    int b = blockIdx.x, t = threadIdx.x;
    int i = b * SCAN_CH + t;
    int v = (i < NN) ? g_deg[i] : 0;
    sh[t] = v;
    __syncthreads();
    for (int off = 1; off < SCAN_CH; off <<= 1) {
        int a = (t >= off) ? sh[t - off] : 0;
        __syncthreads();
        sh[t] += a;
        __syncthreads();
    }
    if (i < NN) g_rowptr[i] = g_boff[b] + sh[t] - v;  // exclusive global prefix
}

__global__ void k_fill(const int* __restrict__ src, const int* __restrict__ dst) {
    int e = blockIdx.x * blockDim.x + threadIdx.x;
    if (e >= NE) return;
    int d = dst[e];
    int pos = g_rowptr[d] + atomicAdd(&g_cursor[d], 1);
    g_csrsrc[pos] = src[e];
}

// ---------------------------------------------------------------------------
// Aggregation: warp per node, float4 per lane, gather-only
// ---------------------------------------------------------------------------
__global__ void __launch_bounds__(256) k_agg() {
    int w = blockIdx.x * 8 + (threadIdx.x >> 5);
    if (w >= NN) return;
    int lane = threadIdx.x & 31;
    int beg = g_rowptr[w], end = g_rowptr[w + 1];
    float4 acc = make_float4(0.f, 0.f, 0.f, 0.f);
    for (int e = beg; e < end; e++) {
        int s = g_csrsrc[e];
        float4 v = reinterpret_cast<const float4*>(g_h + (size_t)s * HD)[lane];
        acc.x += v.x; acc.y += v.y; acc.z += v.z; acc.w += v.w;
    }
    int cnt = end - beg;
    float inv = 1.0f / (float)(cnt > 0 ? cnt : 1);
    float vv[4] = {acc.x * inv, acc.y * inv, acc.z * inv, acc.w * inv};
    size_t o = (size_t)w * 256 + lane * 4;
#pragma unroll
    for (int j = 0; j < 4; j++) {
        __nv_bfloat16 hi = __float2bfloat16(vv[j]);
        g_Ahi[o + j] = hi;
        g_Alo[o + j] = __float2bfloat16(vv[j] - __bfloat162float(hi));
    }
}

// ---------------------------------------------------------------------------
// GEMM core: 256 threads, CTA tile 128(M) x 128(N), K chunks of 64 staged in
// swizzled smem. Warp tile 64x32 (2x4 warp grid). bf16 hi/lo 3-term split.
// SMEM layout: AHI 0, ALO 16K, BHI 32K, BLO 48K  (total 64KB dynamic)
// ---------------------------------------------------------------------------
#define SM_AHI 0
#define SM_ALO 16384
#define SM_BHI 32768
#define SM_BLO 49152
#define SM_BYTES 65536

struct Frags {
    float acc[4][4][4];
};

__device__ __forceinline__ void gemm_chunk_compute(uint32_t sb, int wid, int lane,
                                                   float acc[4][4][4]) {
    int m_base = (wid >> 2) * 64;
    int n_base = (wid & 3) * 32;
#pragma unroll
    for (int ks = 0; ks < 4; ks++) {
        uint32_t a_hi[4][4], a_lo[4][4];
#pragma unroll
        for (int mt = 0; mt < 4; mt++) {
            int row = m_base + mt * 16 + (lane & 15);
            int col = ks * 16 + ((lane >> 4) << 3);
            uint32_t ad = sb + SM_AHI + swz((uint32_t)(row * 128 + col * 2));
            ldsm4(a_hi[mt], ad);
            ldsm4(a_lo[mt], ad + (SM_ALO - SM_AHI));
        }
        uint32_t b_hi[2][4], b_lo[2][4];
#pragma unroll
        for (int nt2 = 0; nt2 < 2; nt2++) {
            int nrow = n_base + nt2 * 16 + (lane & 7) + (((lane >> 4) & 1) << 3);
            int col = ks * 16 + (((lane >> 3) & 1) << 3);
            uint32_t bd = sb + SM_BHI + swz((uint32_t)(nrow * 128 + col * 2));
            ldsm4(b_hi[nt2], bd);
            ldsm4(b_lo[nt2], bd + (SM_BLO - SM_BHI));
        }
#pragma unroll
        for (int mt = 0; mt < 4; mt++) {
#pragma unroll
            for (int nt = 0; nt < 4; nt++) {
                const uint32_t* bh = &b_hi[nt >> 1][(nt & 1) * 2];
                const uint32_t* bl = &b_lo[nt >> 1][(nt & 1) * 2];
                mma_bf16(acc[mt][nt], a_hi[mt], bh);
                mma_bf16(acc[mt][nt], a_lo[mt], bh);
                mma_bf16(acc[mt][nt], a_hi[mt], bl);
            }
        }
    }
}

// Layer GEMM: A = g_A(hi/lo) full 256 cols (mean||self), B = g_B(hi/lo)[layer],
// epilogue: bias + relu -> g_h, g_Ahi/g_Alo self halves.
__global__ void __launch_bounds__(256) k_layer_gemm(const float* __restrict__ bias, int layer) {
    extern __shared__ __align__(1024) char smem[];
    uint32_t sb = smem_to_u32(smem);
    int tid = threadIdx.x, wid = tid >> 5, lane = tid & 31;
    int base = blockIdx.x * 128;

    const __nv_bfloat16* Bh = g_Bhi + (size_t)layer * HD * 256;
    const __nv_bfloat16* Bl = g_Blo + (size_t)layer * HD * 256;

    float acc[4][4][4];
#pragma unroll
    for (int i = 0; i < 4; i++)
#pragma unroll
        for (int j = 0; j < 4; j++)
#pragma unroll
            for (int q = 0; q < 4; q++) acc[i][j][q] = 0.f;

    for (int kc = 0; kc < 4; kc++) {
        int k0 = kc * 64;
        if (kc) __syncthreads();  // protect previous chunk's reads
        for (int idx = tid; idx < 1024; idx += 256) {
            int r = idx >> 3, s = idx & 7;
            int node = base + r; if (node >= NN) node = NN - 1;
            size_t ga = (size_t)node * 256 + k0 + s * 8;
            size_t gb = (size_t)r * 256 + k0 + s * 8;
            uint32_t so = swz((uint32_t)(r * 128 + s * 16));
            *reinterpret_cast<uint4*>(smem + SM_AHI + so) = *reinterpret_cast<const uint4*>(g_Ahi + ga);
            *reinterpret_cast<uint4*>(smem + SM_ALO + so) = *reinterpret_cast<const uint4*>(g_Alo + ga);
            *reinterpret_cast<uint4*>(smem + SM_BHI + so) = *reinterpret_cast<const uint4*>(Bh + gb);
            *reinterpret_cast<uint4*>(smem + SM_BLO + so) = *reinterpret_cast<const uint4*>(Bl + gb);
        }
        __syncthreads();
        gemm_chunk_compute(sb, wid, lane, acc);
    }

    // Epilogue: bias + relu, write fp32 + hi/lo bf16 self features
    int gid = lane >> 2, itg = lane & 3;
    int m_base = (wid >> 2) * 64, n_base = (wid & 3) * 32;
#pragma unroll
    for (int mt = 0; mt < 4; mt++) {
#pragma unroll
        for (int nt = 0; nt < 4; nt++) {
            int col = n_base + nt * 8 + itg * 2;
            float b0 = bias[col], b1 = bias[col + 1];
#pragma unroll
            for (int half = 0; half < 2; half++) {
                int node = base + m_base + mt * 16 + gid + half * 8;
                if (node >= NN) continue;
                float v0 = acc[mt][nt][half * 2 + 0] + b0;
                float v1 = acc[mt][nt][half * 2 + 1] + b1;
                v0 = v0 > 0.f ? v0 : 0.f;
                v1 = v1 > 0.f ? v1 : 0.f;
                *reinterpret_cast<float2*>(g_h + (size_t)node * HD + col) = make_float2(v0, v1);
                __nv_bfloat16 h0 = __float2bfloat16(v0), h1 = __float2bfloat16(v1);
                __nv_bfloat16 l0 = __float2bfloat16(v0 - __bfloat162float(h0));
                __nv_bfloat16 l1 = __float2bfloat16(v1 - __bfloat162float(h1));
                size_t o = (size_t)node * 256 + 128 + col;
                *reinterpret_cast<__nv_bfloat162*>(&g_Ahi[o]) = __nv_bfloat162{h0, h1};
                *reinterpret_cast<__nv_bfloat162*>(&g_Alo[o]) = __nv_bfloat162{l0, l1};
            }
        }
    }
}

// Final GEMM: logits tile 128(M) x 128(N of vocab), K = 128 (self features),
// epilogue: + blast, write to d_out (cols < 1000).
__global__ void __launch_bounds__(256) k_final_gemm(const float* __restrict__ blast,
                                                    float* __restrict__ out) {
    extern __shared__ __align__(1024) char smem[];
    uint32_t sb = smem_to_u32(smem);
    int tid = threadIdx.x, wid = tid >> 5, lane = tid & 31;
    int base = blockIdx.x * 128;
    int ncol0 = blockIdx.y * 128;

    float acc[4][4][4];
#pragma unroll
    for (int i = 0; i < 4; i++)
#pragma unroll
        for (int j = 0; j < 4; j++)
#pragma unroll
            for (int q = 0; q < 4; q++) acc[i][j][q] = 0.f;

    for (int kc = 0; kc < 2; kc++) {
        int k0 = kc * 64;
        if (kc) __syncthreads();
        for (int idx = tid; idx < 1024; idx += 256) {
            int r = idx >> 3, s = idx & 7;
            int node = base + r; if (node >= NN) node = NN - 1;
            size_t ga = (size_t)node * 256 + 128 + k0 + s * 8;
            size_t gb = (size_t)(ncol0 + r) * HD + k0 + s * 8;
            uint32_t so = swz((uint32_t)(r * 128 + s * 16));
            *reinterpret_cast<uint4*>(smem + SM_AHI + so) = *reinterpret_cast<const uint4*>(g_Ahi + ga);
            *reinterpret_cast<uint4*>(smem + SM_ALO + so) = *reinterpret_cast<const uint4*>(g_Alo + ga);
            *reinterpret_cast<uint4*>(smem + SM_BHI + so) = *reinterpret_cast<const uint4*>(g_BLhi + gb);
            *reinterpret_cast<uint4*>(smem + SM_BLO + so) = *reinterpret_cast<const uint4*>(g_BLlo + gb);
        }
        __syncthreads();
        gemm_chunk_compute(sb, wid, lane, acc);
    }

    int gid = lane >> 2, itg = lane & 3;
    int m_base = (wid >> 2) * 64, n_base = (wid & 3) * 32;
#pragma unroll
    for (int mt = 0; mt < 4; mt++) {
#pragma unroll
        for (int nt = 0; nt < 4; nt++) {
            int col = ncol0 + n_base + nt * 8 + itg * 2;
            if (col >= VC) continue;
            float b0 = blast[col];
            float b1 = (col + 1 < VC) ? blast[col + 1] : 0.f;
#pragma unroll
            for (int half = 0; half < 2; half++) {
                int node = base + m_base + mt * 16 + gid + half * 8;
                if (node >= NN) continue;
                float v0 = acc[mt][nt][half * 2 + 0] + b0;
                float v1 = acc[mt][nt][half * 2 + 1] + b1;
                size_t o = (size_t)node * VC + col;
                out[o] = v0;
                if (col + 1 < VC) out[o + 1] = v1;
            }
        }
    }
}

// ---------------------------------------------------------------------------
// Softmax: warp per row, 1000 cols held in registers (32 per lane)
// ---------------------------------------------------------------------------
__global__ void __launch_bounds__(256) k_softmax(float* __restrict__ out) {
    int w = blockIdx.x * 8 + (threadIdx.x >> 5);
    if (w >= NN) return;
    int lane = threadIdx.x & 31;
    float r[32];
    float mx = -1e30f;
    float* row = out + (size_t)w * VC;
#pragma unroll
    for (int i = 0; i < 32; i++) {
        int c = lane + i * 32;
        float v = (c < VC) ? row[c] : -1e30f;
        r[i] = v;
        mx = fmaxf(mx, v);
    }
#pragma unroll
    for (int o = 16; o > 0; o >>= 1) mx = fmaxf(mx, __shfl_xor_sync(0xFFFFFFFF, mx, o));
    float sum = 0.f;
#pragma unroll
    for (int i = 0; i < 32; i++) {
        int c = lane + i * 32;
        if (c < VC) { r[i] = __expf(r[i] - mx); sum += r[i]; }
    }
#pragma unroll
    for (int o = 16; o > 0; o >>= 1) sum += __shfl_xor_sync(0xFFFFFFFF, sum, o);
    float inv = 1.0f / sum;
#pragma unroll
    for (int i = 0; i < 32; i++) {
        int c = lane + i * 32;
        if (c < VC) row[c] = r[i] * inv;
    }
}

// ---------------------------------------------------------------------------
// Launch
// ---------------------------------------------------------------------------
extern "C" void kernel_launch(void* const* d_in, const int* in_sizes, int n_in,
                              void* d_out, int out_size) {
    const int*   x     = (const int*)d_in[0];
    const int*   ei    = (const int*)d_in[1];
    const float* emb   = (const float*)d_in[2];
    const float* Wl    = (const float*)d_in[3];
    const float* bl    = (const float*)d_in[4];
    const float* Wr    = (const float*)d_in[5];
    const float* Wlast = (const float*)d_in[6];
    const float* blast = (const float*)d_in[7];
    float* out = (float*)d_out;
    const int* src = ei;
    const int* dst = ei + NE;

    cudaFuncSetAttribute(k_layer_gemm, cudaFuncAttributeMaxDynamicSharedMemorySize, SM_BYTES);
    cudaFuncSetAttribute(k_final_gemm, cudaFuncAttributeMaxDynamicSharedMemorySize, SM_BYTES);

    k_zero<<<(NN + 255) / 256, 256>>>();
    k_embed<<<(NN * 32 + 255) / 256, 256>>>(x, emb);
    k_prep_w<<<(NL * HD * 2 * HD + VP * HD + 255) / 256, 256>>>(Wl, Wr, Wlast);
    k_deg<<<(NE + 255) / 256, 256>>>(dst);
    k_scan_partial<<<SCAN_NB, SCAN_CH>>>();
    k_scan_top<<<1, 256>>>();
    k_scan_apply<<<SCAN_NB, SCAN_CH>>>();
    k_fill<<<(NE + 255) / 256, 256>>>(src, dst);

    int nb = (NN + 127) / 128;
    for (int l = 0; l < NL; l++) {
        k_agg<<<(NN + 7) / 8, 256>>>();
        k_layer_gemm<<<nb, 256, SM_BYTES>>>(bl + l * HD, l);
    }

    dim3 fgrid(nb, VP / 128);
    k_final_gemm<<<fgrid, 256, SM_BYTES>>>(blast, out);
    k_softmax<<<(NN + 7) / 8, 256>>>(out);
}